// round 11
// baseline (speedup 1.0000x reference)
#include <cuda_runtime.h>
#include <cuda_fp16.h>
#include <cstdint>

#define D        128
#define NUM_DOW  7
#define NUM_TOD  288
#define NROWS    (NUM_DOW * NUM_TOD)   // 2016
#define RPB      8                     // rows per build block -> 252 blocks
#define TPW      16                    // tokens per warp in gather

// Precomputed output rows for every (dow, tod) pair, fp16: 2016*128*2B = 504 KB.
__device__ __align__(16) __half g_table[NROWS * D];

// ---------------------------------------------------------------------------
// Kernel 1: build the 2016-row table (fp32 math, fp16 store).
//   table[row][e] = relu(W1[dow] + W1[7+tod] + b1) dot W2[:, e] + b2[e]
// 252 blocks x 256 threads; thread = (e, half), 4 rows per thread.
// ---------------------------------------------------------------------------
__global__ __launch_bounds__(256, 4)
void build_table_kernel(const float* __restrict__ W1,
                        const float* __restrict__ b1,
                        const float* __restrict__ W2,
                        const float* __restrict__ b2) {
    __shared__ __align__(16) float h[RPB][D];

    const int e     = threadIdx.x & (D - 1);
    const int half  = threadIdx.x >> 7;
    const int rbase = half * (RPB / 2);
    const int row0  = blockIdx.x * RPB;

    const float b1e = __ldg(b1 + e);
    #pragma unroll
    for (int i = 0; i < RPB / 2; i++) {
        const int r   = rbase + i;
        const int row = row0 + r;
        const int dow = row / NUM_TOD;
        const int tod = row - dow * NUM_TOD;
        const float v = __ldg(W1 + dow * D + e)
                      + __ldg(W1 + (NUM_DOW + tod) * D + e) + b1e;
        h[r][e] = fmaxf(v, 0.0f);
    }
    __syncthreads();

    float acc[RPB / 2];
    const float b2e = __ldg(b2 + e);
    #pragma unroll
    for (int i = 0; i < RPB / 2; i++) acc[i] = b2e;

    const float4* __restrict__ h4 = (const float4*)&h[0][0];  // [RPB][32]

    #pragma unroll 4
    for (int d4 = 0; d4 < D / 4; d4++) {
        const float w0 = __ldg(W2 + (4 * d4 + 0) * D + e);
        const float w1 = __ldg(W2 + (4 * d4 + 1) * D + e);
        const float w2 = __ldg(W2 + (4 * d4 + 2) * D + e);
        const float w3 = __ldg(W2 + (4 * d4 + 3) * D + e);
        #pragma unroll
        for (int i = 0; i < RPB / 2; i++) {
            const float4 hv = h4[(rbase + i) * (D / 4) + d4];
            acc[i] = fmaf(hv.x, w0, acc[i]);
            acc[i] = fmaf(hv.y, w1, acc[i]);
            acc[i] = fmaf(hv.z, w2, acc[i]);
            acc[i] = fmaf(hv.w, w3, acc[i]);
        }
    }

    #pragma unroll
    for (int i = 0; i < RPB / 2; i++)
        g_table[(size_t)(row0 + rbase + i) * D + e] = __float2half(acc[i]);
}

// ---------------------------------------------------------------------------
// Kernel 2: gather, 16 tokens per warp with paired-row 128-bit loads.
// fp16 row = 256 B = 16 lanes x 16 B, so one LDG.128 serves TWO tokens:
//   lanes 0-15  (half=0) read token 2p,  lanes 16-31 (half=1) read 2p+1.
// __ldcg keeps the random table reads out of L1 (zero-reuse there).
// Each thread converts its 16 B (8 halfs) -> 32 B fp32 and writes one
// STG.256 (st.global.v8.f32); warp stores 1024 B/instr, fully coalesced.
// Per warp: 1 TE load + 8 table LDG.128 + 8 STG.256 for 16 tokens.
// ntok % 16 == 0 (131072).
// ---------------------------------------------------------------------------
__global__ __launch_bounds__(256)
void gather_kernel(const int2* __restrict__ TE,   // [ntok] (dow_raw, tod_raw)
                   float* __restrict__ out,       // [ntok * 128] fp32
                   int ntok) {
    const int warp = (int)((blockIdx.x * blockDim.x + threadIdx.x) >> 5);
    const int lane = threadIdx.x & 31;
    const int half = lane >> 4;        // which token of each pair
    const int sub  = lane & 15;        // 16 B chunk within the 256 B row
    const int t0   = warp * TPW;
    if (t0 >= ntok) return;

    // 16 distinct TE pairs per warp (2-way broadcast per address).
    const int2 te = __ldg(TE + t0 + (lane & 15));
    const unsigned myrow =
        ((unsigned)te.x % NUM_DOW) * NUM_TOD + ((unsigned)te.y % NUM_TOD);

    unsigned rows[TPW / 2];
    #pragma unroll
    for (int p = 0; p < TPW / 2; p++)          // row for token t0 + 2p + half
        rows[p] = __shfl_sync(0xFFFFFFFFu, myrow, 2 * p + half);

    const float4* __restrict__ tab = (const float4*)g_table;  // 16 f4 per row

    float4 v[TPW / 2];
    #pragma unroll
    for (int p = 0; p < TPW / 2; p++)          // 8 independent L2-only reads
        v[p] = __ldcg(tab + (size_t)rows[p] * (D / 8) + sub);

    #pragma unroll
    for (int p = 0; p < TPW / 2; p++) {
        const __half2* hp = (const __half2*)&v[p];
        const float2 f0 = __half22float2(hp[0]);
        const float2 f1 = __half22float2(hp[1]);
        const float2 f2 = __half22float2(hp[2]);
        const float2 f3 = __half22float2(hp[3]);
        // token t0+2p+half, fp32 bytes [32*sub, 32*sub+32)
        float* dst = out + (size_t)(t0 + 2 * p + half) * D + 8 * sub;
        asm volatile(
            "st.global.v8.f32 [%0], {%1,%2,%3,%4,%5,%6,%7,%8};"
            :: "l"(dst),
               "f"(f0.x), "f"(f0.y), "f"(f1.x), "f"(f1.y),
               "f"(f2.x), "f"(f2.y), "f"(f3.x), "f"(f3.y)
            : "memory");
    }
}

// ---------------------------------------------------------------------------
// Inputs (metadata order): TE, T, W1, b1, W2, b2. T unused.
// Output: [B, S, 1, D] float32 — contiguous, identical to [ntok, D].
// ---------------------------------------------------------------------------
extern "C" void kernel_launch(void* const* d_in, const int* in_sizes, int n_in,
                              void* d_out, int out_size) {
    const int2*  TE = (const int2*)d_in[0];
    const float* W1 = (const float*)d_in[2];
    const float* b1 = (const float*)d_in[3];
    const float* W2 = (const float*)d_in[4];
    const float* b2 = (const float*)d_in[5];

    const int ntok = in_sizes[0] / 2;   // B*S = 131072 (multiple of 16)

    build_table_kernel<<<NROWS / RPB, 256>>>(W1, b1, W2, b2);

    // 16 tokens/warp, 8 warps/block -> 128 tokens per block.
    const int nblocks = (ntok + 8 * TPW - 1) / (8 * TPW);   // 1024
    gather_kernel<<<nblocks, 256>>>(TE, (float*)d_out, ntok);
}